// round 9
// baseline (speedup 1.0000x reference)
#include <cuda_runtime.h>
#include <math.h>
#include <stdint.h>

#define DIMC 768
#define NH 8
#define HD 96
#define BATCH 4
#define SEQ 2048
#define MTOT (BATCH*SEQ)

// Scratch (static device arrays; no cudaMalloc allowed)
__device__ float g_q[(size_t)BATCH*NH*SEQ*HD];
__device__ float g_k[(size_t)BATCH*NH*SEQ*HD];
__device__ float g_vt[(size_t)BATCH*NH*HD*SEQ];    // V transposed: [b,h,d,t]
__device__ float g_att[(size_t)MTOT*DIMC];
__device__ float g_xr[(size_t)MTOT*DIMC];          // tf32-rounded x
__device__ float g_wqr[(size_t)3*DIMC*DIMC];       // tf32-rounded w_qkv
__device__ float g_wpr[(size_t)DIMC*DIMC];         // tf32-rounded w_proj

// ---------------------------------------------------------------------------
// helpers
// ---------------------------------------------------------------------------
__device__ __forceinline__ uint32_t smem_u32(const void* p) {
    uint32_t a;
    asm("{ .reg .u64 t; cvta.to.shared.u64 t, %1; cvt.u32.u64 %0, t; }" : "=r"(a) : "l"(p));
    return a;
}
__device__ __forceinline__ void cp16(uint32_t s, const void* g) {
    asm volatile("cp.async.ca.shared.global [%0], [%1], 16;" :: "r"(s), "l"(g) : "memory");
}
__device__ __forceinline__ void cp_commit() {
    asm volatile("cp.async.commit_group;" ::: "memory");
}
__device__ __forceinline__ void cp_wait1() {
    asm volatile("cp.async.wait_group 1;" ::: "memory");
}
__device__ __forceinline__ uint32_t f2tf(float x) {
    uint32_t r;
    asm("cvt.rna.tf32.f32 %0, %1;" : "=r"(r) : "f"(x));
    return r;
}
__device__ __forceinline__ void ldsm4(uint32_t& r0, uint32_t& r1, uint32_t& r2,
                                      uint32_t& r3, uint32_t addr) {
    asm volatile("ldmatrix.sync.aligned.m8n8.x4.shared.b16 {%0,%1,%2,%3}, [%4];"
                 : "=r"(r0), "=r"(r1), "=r"(r2), "=r"(r3) : "r"(addr));
}
__device__ __forceinline__ void mma_tf(float d[4], uint32_t a0, uint32_t a1,
                                       uint32_t a2, uint32_t a3,
                                       uint32_t b0, uint32_t b1) {
    asm volatile(
        "mma.sync.aligned.m16n8k8.row.col.f32.tf32.tf32.f32 "
        "{%0,%1,%2,%3},{%4,%5,%6,%7},{%8,%9},{%0,%1,%2,%3};"
        : "+f"(d[0]), "+f"(d[1]), "+f"(d[2]), "+f"(d[3])
        : "r"(a0), "r"(a1), "r"(a2), "r"(a3), "r"(b0), "r"(b1));
}

// ---------------------------------------------------------------------------
// round-to-tf32 copy
// ---------------------------------------------------------------------------
__global__ __launch_bounds__(256)
void round_tf_kernel(const float* __restrict__ src, float* __restrict__ dst, int n4)
{
    int i = blockIdx.x * blockDim.x + threadIdx.x;
    if (i < n4) {
        float4 v = ((const float4*)src)[i];
        v.x = __uint_as_float(f2tf(v.x));
        v.y = __uint_as_float(f2tf(v.y));
        v.z = __uint_as_float(f2tf(v.z));
        v.w = __uint_as_float(f2tf(v.w));
        ((float4*)dst)[i] = v;
    }
}

// ---------------------------------------------------------------------------
// GEMM v6: tf32 mma, CTA tile 128(M) x BN(N), 8 warps (2x4), warp tile 64x(BN/4).
// 3-stage cp.async ring, ldmatrix fragments.
// MODE 0: scatter into g_q/g_k/g_vt(transposed). MODE 1: write Cout.
// ---------------------------------------------------------------------------
#define GSTR 36                       // f32 row stride (32 + 4 pad)

template<int MODE, int BN>
__global__ __launch_bounds__(256, 1)
void gemm_tf32(const float* __restrict__ A, const float* __restrict__ W,
               const float* __restrict__ bias, float* __restrict__ Cout)
{
    constexpr int ASZ = 128 * GSTR;
    constexpr int WSZ = BN * GSTR;
    constexpr int STG = ASZ + WSZ;
    constexpr int WNW = BN / 4;       // warp n-width
    constexpr int NT  = WNW / 8;      // n-tiles per warp
    constexpr int NBK = WNW / 16;     // b ldsm4 count
    constexpr int NIT = (128 + BN) / 32;

    extern __shared__ float smf[];
    uint32_t smb = smem_u32(smf);

    int tid = threadIdx.x;
    int lane = tid & 31;
    int wid = tid >> 5;              // 0..7
    int g = lane >> 2, j = lane & 3;
    int wm = wid & 1, wn = wid >> 1; // 2 x 4 warp grid
    int m0 = blockIdx.y * 128;
    int n0 = blockIdx.x * BN;

    auto issue = [&](int c) {
        uint32_t stb = smb + (uint32_t)((c % 3) * STG) * 4;
#pragma unroll
        for (int it = 0; it < NIT; it++) {
            int f = tid + it * 256;
            int row = f >> 3;
            int c4 = (f & 7) * 4;
            if (it < 4) {
                cp16(stb + (uint32_t)(row * GSTR + c4) * 4,
                     A + (size_t)(m0 + row) * DIMC + c * 32 + c4);
            } else {
                int wrow = row - 128;
                cp16(stb + (uint32_t)(ASZ + wrow * GSTR + c4) * 4,
                     W + (size_t)(n0 + wrow) * DIMC + c * 32 + c4);
            }
        }
    };

    int aRowB = wm * 64 + ((lane >> 3) & 1) * 8 + (lane & 7);   // + mt*16
    int aColW = (lane >> 4) * 4;                                // + ks*8
    int bRowB = wn * WNW + ((lane >> 4) & 1) * 8 + (lane & 7);  // + bk*16
    int bColW = ((lane >> 3) & 1) * 4;                          // + ks*8

    float Cf[4][NT][4];
#pragma unroll
    for (int mt = 0; mt < 4; mt++)
#pragma unroll
        for (int nt = 0; nt < NT; nt++)
#pragma unroll
            for (int r = 0; r < 4; r++) Cf[mt][nt][r] = 0.f;

    issue(0); cp_commit();
    issue(1); cp_commit();

    const int NC = DIMC / 32;   // 24
    for (int c = 0; c < NC; c++) {
        cp_wait1();
        __syncthreads();
        if (c + 2 < NC) issue(c + 2);
        cp_commit();

        uint32_t stA = smb + (uint32_t)((c % 3) * STG) * 4;
        uint32_t stW = stA + (uint32_t)ASZ * 4;

#pragma unroll
        for (int ks = 0; ks < 4; ks++) {
            uint32_t a[4][4], b[NT][2];
#pragma unroll
            for (int mt = 0; mt < 4; mt++)
                ldsm4(a[mt][0], a[mt][1], a[mt][2], a[mt][3],
                      stA + (uint32_t)((aRowB + mt * 16) * GSTR + ks * 8 + aColW) * 4);
#pragma unroll
            for (int bk = 0; bk < NBK; bk++)
                ldsm4(b[2*bk][0], b[2*bk][1], b[2*bk+1][0], b[2*bk+1][1],
                      stW + (uint32_t)((bRowB + bk * 16) * GSTR + ks * 8 + bColW) * 4);
#pragma unroll
            for (int mt = 0; mt < 4; mt++)
#pragma unroll
                for (int nt = 0; nt < NT; nt++)
                    mma_tf(Cf[mt][nt], a[mt][0], a[mt][1], a[mt][2], a[mt][3],
                           b[nt][0], b[nt][1]);
        }
    }

    // epilogue
#pragma unroll
    for (int mt = 0; mt < 4; mt++) {
        int row0 = m0 + wm * 64 + mt * 16 + g;
#pragma unroll
        for (int nt = 0; nt < NT; nt++) {
            int col = n0 + wn * WNW + nt * 8 + 2 * j;
            float b0 = bias[col], b1 = bias[col + 1];
            float2 v0 = make_float2(Cf[mt][nt][0] + b0, Cf[mt][nt][1] + b1);
            float2 v1 = make_float2(Cf[mt][nt][2] + b0, Cf[mt][nt][3] + b1);
            if (MODE == 1) {
                *(float2*)(Cout + (size_t)row0 * DIMC + col) = v0;
                *(float2*)(Cout + (size_t)(row0 + 8) * DIMC + col) = v1;
            } else {
                int s = (col >= 2 * DIMC) ? 2 : (col >= DIMC ? 1 : 0);
                int rr = col - s * DIMC;
                int hh = rr / HD;
                int d = rr - hh * HD;
                int bb0 = row0 >> 11, t0 = row0 & (SEQ - 1);
                int r1 = row0 + 8;
                int bb1 = r1 >> 11, t1 = r1 & (SEQ - 1);
                if (s == 2) {
                    float* dv0 = g_vt + ((size_t)(bb0 * NH + hh) * HD + d) * SEQ + t0;
                    dv0[0] = v0.x; dv0[SEQ] = v0.y;
                    float* dv1 = g_vt + ((size_t)(bb1 * NH + hh) * HD + d) * SEQ + t1;
                    dv1[0] = v1.x; dv1[SEQ] = v1.y;
                } else {
                    float* base = (s == 0) ? g_q : g_k;
                    *(float2*)(base + ((size_t)(bb0 * NH + hh) * SEQ + t0) * HD + d) = v0;
                    *(float2*)(base + ((size_t)(bb1 * NH + hh) * SEQ + t1) * HD + d) = v1;
                }
            }
        }
    }
}

#define GEMM_SMEM_256 (3*(128+256)*GSTR*4)
#define GEMM_SMEM_128 (3*(128+128)*GSTR*4)

// ---------------------------------------------------------------------------
// RoPE in place on g_q, g_k.
// ---------------------------------------------------------------------------
__global__ __launch_bounds__(256)
void rope_kernel()
{
    int idx = blockIdx.x * blockDim.x + threadIdx.x;
    int j = idx % 48;
    int rest = idx / 48;
    int t = rest & (SEQ - 1);
    int bh = rest >> 11;

    float freq = exp2f(-(2.f * j / 96.f) * 13.287712379549449f);
    float ang = (float)t * freq;
    float sn, cs;
    sincosf(ang, &sn, &cs);

    size_t base = ((size_t)bh * SEQ + t) * HD;
    float q1 = g_q[base + j], q2 = g_q[base + j + 48];
    g_q[base + j]      = q1 * cs - q2 * sn;
    g_q[base + j + 48] = q2 * cs + q1 * sn;
    float k1 = g_k[base + j], k2 = g_k[base + j + 48];
    g_k[base + j]      = k1 * cs - k2 * sn;
    g_k[base + j + 48] = k2 * cs + k1 * sn;
}

// ---------------------------------------------------------------------------
// Flash attention v4: delayed-PV pipeline. Per tile: S(kt) and PV(kt-1) issue
// back-to-back (192 contiguous MMAs); softmax(kt) overlaps other warps' MMA.
// P(kt) kept as tf32 A-fragments (pa) for next iteration's PV.
// ---------------------------------------------------------------------------
#define QLD 100
#define KLD 100
#define VTLD 68
#define KVSTG (64*KLD + 96*VTLD)
#define ATTN_SMEM ((128*QLD + 3*KVSTG) * 4)   // 206336

__global__ __launch_bounds__(256, 1)
void attn_mma()
{
    extern __shared__ float smf[];
    float* Qs = smf;
    float* KV = smf + 128 * QLD;

    int qt = gridDim.x - 1 - blockIdx.x;
    int hh = blockIdx.y, b = blockIdx.z;
    int tid = threadIdx.x;
    int lane = tid & 31;
    int wid = tid >> 5;
    int g = lane >> 2, j = lane & 3;
    const float scale = rsqrtf((float)HD);

    const float* Qg = g_q + ((size_t)(b * NH + hh) * SEQ + (size_t)qt * 128) * HD;
    const float* Kg = g_k + ((size_t)(b * NH + hh) * SEQ) * HD;
    const float* Vtg = g_vt + ((size_t)(b * NH + hh) * HD) * SEQ;

    int nkt = 2 * qt + 2;

    auto issue_kv = [&](int kt) {
        int st = kt % 3;
        float* Ks = KV + st * KVSTG;
        float* Vs = Ks + 64 * KLD;
        const float* kp = Kg + (size_t)kt * 64 * HD;
#pragma unroll
        for (int it = 0; it < 6; it++) {
            int f = tid + it * 256;
            int r = f / 24, c4 = (f % 24) * 4;
            cp16(smem_u32(Ks + r * KLD + c4), kp + (size_t)r * HD + c4);
        }
        const float* vp = Vtg + kt * 64;
#pragma unroll
        for (int it = 0; it < 6; it++) {
            int f = tid + it * 256;
            int d = f >> 4, c4 = (f & 15) * 4;
            cp16(smem_u32(Vs + d * VTLD + c4), vp + (size_t)d * SEQ + c4);
        }
    };

    issue_kv(0); cp_commit();
    issue_kv(1); cp_commit();

    for (int f = tid; f < 128 * 24; f += 256) {
        int r = f / 24, c4 = (f % 24) * 4;
        float4 v = *(const float4*)(Qg + (size_t)r * HD + c4);
        v.x = __uint_as_float(f2tf(v.x * scale));
        v.y = __uint_as_float(f2tf(v.y * scale));
        v.z = __uint_as_float(f2tf(v.z * scale));
        v.w = __uint_as_float(f2tf(v.w * scale));
        *(float4*)(Qs + r * QLD + c4) = v;
    }

    uint32_t qsb = smem_u32(Qs);
    uint32_t kvb = smem_u32(KV);
    int qRow = wid * 16 + ((lane >> 3) & 1) * 8 + (lane & 7);
    int qColW = (lane >> 4) * 4;
    int bRow = ((lane >> 4) & 1) * 8 + (lane & 7);
    int bColW = ((lane >> 3) & 1) * 4;

    float m0r = -1e30f, m1r = -1e30f, l0r = 0.f, l1r = 0.f;
    float O[12][4];
    uint32_t pa[8][4];   // P(kt-1) as tf32 A-fragments
#pragma unroll
    for (int nt = 0; nt < 12; nt++)
#pragma unroll
        for (int r = 0; r < 4; r++) O[nt][r] = 0.f;

    int row0 = qt * 128 + wid * 16 + g;
    int src_lo = (lane & ~3) | (j >> 1);
    int par = j & 1;

    for (int kt = 0; kt < nkt; kt++) {
        cp_wait1();
        __syncthreads();          // stage kt visible

        uint32_t ksb = kvb + (uint32_t)((kt % 3) * KVSTG) * 4;

        // ---- S = Q @ K^T (stage kt) ----
        float S[8][4];
#pragma unroll
        for (int nt = 0; nt < 8; nt++)
#pragma unroll
            for (int r = 0; r < 4; r++) S[nt][r] = 0.f;

#pragma unroll
        for (int ks = 0; ks < 12; ks++) {
            uint32_t a0, a1, a2, a3;
            ldsm4(a0, a1, a2, a3, qsb + (uint32_t)(qRow * QLD + ks * 8 + qColW) * 4);
            uint32_t bfr[8][2];
#pragma unroll
            for (int bk = 0; bk < 4; bk++)
                ldsm4(bfr[2*bk][0], bfr[2*bk][1], bfr[2*bk+1][0], bfr[2*bk+1][1],
                      ksb + (uint32_t)((bRow + bk * 16) * KLD + ks * 8 + bColW) * 4);
#pragma unroll
            for (int nt = 0; nt < 8; nt++)
                mma_tf(S[nt], a0, a1, a2, a3, bfr[nt][0], bfr[nt][1]);
        }

        // ---- PV: O += P(kt-1) @ V(kt-1)  (stage kt-1, still resident) ----
        if (kt > 0) {
            uint32_t vsb = kvb + (uint32_t)(((kt - 1) % 3) * KVSTG + 64 * KLD) * 4;
#pragma unroll
            for (int ks = 0; ks < 8; ks++) {
                uint32_t bfr[12][2];
#pragma unroll
                for (int bk = 0; bk < 6; bk++)
                    ldsm4(bfr[2*bk][0], bfr[2*bk][1], bfr[2*bk+1][0], bfr[2*bk+1][1],
                          vsb + (uint32_t)((bRow + bk * 16) * VTLD + ks * 8 + bColW) * 4);
#pragma unroll
                for (int nt = 0; nt < 12; nt++)
                    mma_tf(O[nt], pa[ks][0], pa[ks][1], pa[ks][2], pa[ks][3],
                           bfr[nt][0], bfr[nt][1]);
            }
        }
        __syncthreads();          // all warps done with stage kt-1
        if (kt + 2 < nkt) issue_kv(kt + 2);   // overwrites slot (kt-1)%3
        cp_commit();

        // ---- mask + online softmax + build pa ----
        if (kt >= nkt - 2) {
            int colb = kt * 64;
#pragma unroll
            for (int nt = 0; nt < 8; nt++) {
                int c0 = colb + nt * 8 + 2 * j;
                if (c0 > row0)     S[nt][0] = -1e30f;
                if (c0 + 1 > row0) S[nt][1] = -1e30f;
                if (c0 > row0 + 8)     S[nt][2] = -1e30f;
                if (c0 + 1 > row0 + 8) S[nt][3] = -1e30f;
            }
        }

        float mx0 = -1e30f, mx1 = -1e30f;
#pragma unroll
        for (int nt = 0; nt < 8; nt++) {
            mx0 = fmaxf(mx0, fmaxf(S[nt][0], S[nt][1]));
            mx1 = fmaxf(mx1, fmaxf(S[nt][2], S[nt][3]));
        }
        mx0 = fmaxf(mx0, __shfl_xor_sync(0xffffffffu, mx0, 1));
        mx0 = fmaxf(mx0, __shfl_xor_sync(0xffffffffu, mx0, 2));
        mx1 = fmaxf(mx1, __shfl_xor_sync(0xffffffffu, mx1, 1));
        mx1 = fmaxf(mx1, __shfl_xor_sync(0xffffffffu, mx1, 2));

        float mn0 = fmaxf(m0r, mx0), mn1 = fmaxf(m1r, mx1);
        float al0 = __expf(m0r - mn0), al1 = __expf(m1r - mn1);
        float s0 = 0.f, s1 = 0.f;
#pragma unroll
        for (int nt = 0; nt < 8; nt++) {
            S[nt][0] = __expf(S[nt][0] - mn0);
            S[nt][1] = __expf(S[nt][1] - mn0);
            S[nt][2] = __expf(S[nt][2] - mn1);
            S[nt][3] = __expf(S[nt][3] - mn1);
            s0 += S[nt][0] + S[nt][1];
            s1 += S[nt][2] + S[nt][3];
        }
        s0 += __shfl_xor_sync(0xffffffffu, s0, 1);
        s0 += __shfl_xor_sync(0xffffffffu, s0, 2);
        s1 += __shfl_xor_sync(0xffffffffu, s1, 1);
        s1 += __shfl_xor_sync(0xffffffffu, s1, 2);
        l0r = l0r * al0 + s0;
        l1r = l1r * al1 + s1;
        m0r = mn0; m1r = mn1;
#pragma unroll
        for (int nt = 0; nt < 12; nt++) {
            O[nt][0] *= al0; O[nt][1] *= al0;
            O[nt][2] *= al1; O[nt][3] *= al1;
        }

        // pa = A-fragment relayout of P (shuffles), tf32-rounded
#pragma unroll
        for (int ks = 0; ks < 8; ks++) {
            float p00 = __shfl_sync(0xffffffffu, S[ks][0], src_lo);
            float p01 = __shfl_sync(0xffffffffu, S[ks][1], src_lo);
            float p10 = __shfl_sync(0xffffffffu, S[ks][0], src_lo + 2);
            float p11 = __shfl_sync(0xffffffffu, S[ks][1], src_lo + 2);
            float p20 = __shfl_sync(0xffffffffu, S[ks][2], src_lo);
            float p21 = __shfl_sync(0xffffffffu, S[ks][3], src_lo);
            float p30 = __shfl_sync(0xffffffffu, S[ks][2], src_lo + 2);
            float p31 = __shfl_sync(0xffffffffu, S[ks][3], src_lo + 2);
            pa[ks][0] = f2tf(par ? p01 : p00);
            pa[ks][1] = f2tf(par ? p21 : p20);
            pa[ks][2] = f2tf(par ? p11 : p10);
            pa[ks][3] = f2tf(par ? p31 : p30);
        }
    }

    // ---- drain: final PV with stage nkt-1 ----
    {
        uint32_t vsb = kvb + (uint32_t)(((nkt - 1) % 3) * KVSTG + 64 * KLD) * 4;
#pragma unroll
        for (int ks = 0; ks < 8; ks++) {
            uint32_t bfr[12][2];
#pragma unroll
            for (int bk = 0; bk < 6; bk++)
                ldsm4(bfr[2*bk][0], bfr[2*bk][1], bfr[2*bk+1][0], bfr[2*bk+1][1],
                      vsb + (uint32_t)((bRow + bk * 16) * VTLD + ks * 8 + bColW) * 4);
#pragma unroll
            for (int nt = 0; nt < 12; nt++)
                mma_tf(O[nt], pa[ks][0], pa[ks][1], pa[ks][2], pa[ks][3],
                       bfr[nt][0], bfr[nt][1]);
        }
    }

    float inv0 = 1.f / l0r, inv1 = 1.f / l1r;
    float* outb = g_att + ((size_t)b * SEQ + row0) * DIMC + hh * HD;
#pragma unroll
    for (int nt = 0; nt < 12; nt++) {
        int d = nt * 8 + 2 * j;
        float2 v0 = make_float2(__uint_as_float(f2tf(O[nt][0] * inv0)),
                                __uint_as_float(f2tf(O[nt][1] * inv0)));
        float2 v1 = make_float2(__uint_as_float(f2tf(O[nt][2] * inv1)),
                                __uint_as_float(f2tf(O[nt][3] * inv1)));
        *(float2*)(outb + d) = v0;
        *(float2*)(outb + (size_t)8 * DIMC + d) = v1;
    }
}

// ---------------------------------------------------------------------------
// Launch
// Inputs: 0=x, 1=mask (ignored, causal), 2=w_qkv, 3=b_qkv, 4=w_proj, 5=b_proj
// ---------------------------------------------------------------------------
extern "C" void kernel_launch(void* const* d_in, const int* in_sizes, int n_in,
                              void* d_out, int out_size)
{
    const float* x      = (const float*)d_in[0];
    const float* w_qkv  = (const float*)d_in[2];
    const float* b_qkv  = (const float*)d_in[3];
    const float* w_proj = (const float*)d_in[4];
    const float* b_proj = (const float*)d_in[5];
    float* out = (float*)d_out;

    cudaFuncSetAttribute(attn_mma, cudaFuncAttributeMaxDynamicSharedMemorySize,
                         ATTN_SMEM);
    cudaFuncSetAttribute((void*)gemm_tf32<0, 256>,
                         cudaFuncAttributeMaxDynamicSharedMemorySize, GEMM_SMEM_256);
    cudaFuncSetAttribute((void*)gemm_tf32<1, 128>,
                         cudaFuncAttributeMaxDynamicSharedMemorySize, GEMM_SMEM_128);

    float *xr, *wqr, *wpr, *attp;
    cudaGetSymbolAddress((void**)&xr,  g_xr);
    cudaGetSymbolAddress((void**)&wqr, g_wqr);
    cudaGetSymbolAddress((void**)&wpr, g_wpr);
    cudaGetSymbolAddress((void**)&attp, g_att);

    // tf32-round operands (removes truncation bias in mma)
    round_tf_kernel<<<(MTOT * DIMC / 4 + 255) / 256, 256>>>(x, xr, MTOT * DIMC / 4);
    round_tf_kernel<<<(3 * DIMC * DIMC / 4 + 255) / 256, 256>>>(w_qkv, wqr, 3 * DIMC * DIMC / 4);
    round_tf_kernel<<<(DIMC * DIMC / 4 + 255) / 256, 256>>>(w_proj, wpr, DIMC * DIMC / 4);

    // QKV: M=8192, N=2304 (CTA tile 128x256)
    gemm_tf32<0, 256><<<dim3(2304 / 256, MTOT / 128), 256, GEMM_SMEM_256>>>(
        xr, wqr, b_qkv, nullptr);

    // RoPE
    rope_kernel<<<(BATCH * NH * SEQ * 48) / 256, 256>>>();

    // Attention
    attn_mma<<<dim3(SEQ / 128, NH, BATCH), 256, ATTN_SMEM>>>();

    // Projection: M=8192, N=768 (CTA tile 128x128, 384 CTAs)
    gemm_tf32<1, 128><<<dim3(DIMC / 128, MTOT / 128), 256, GEMM_SMEM_128>>>(
        attp, wpr, b_proj, out);
}

// round 10
// speedup vs baseline: 1.0406x; 1.0406x over previous
#include <cuda_runtime.h>
#include <math.h>
#include <stdint.h>

#define DIMC 768
#define NH 8
#define HD 96
#define BATCH 4
#define SEQ 2048
#define MTOT (BATCH*SEQ)

// Scratch (static device arrays; no cudaMalloc allowed)
__device__ float g_q[(size_t)BATCH*NH*SEQ*HD];
__device__ float g_k[(size_t)BATCH*NH*SEQ*HD];
__device__ float g_vt[(size_t)BATCH*NH*HD*SEQ];    // V transposed: [b,h,d,t]
__device__ float g_att[(size_t)MTOT*DIMC];
__device__ float g_xr[(size_t)MTOT*DIMC];          // tf32-rounded x
__device__ float g_wqr[(size_t)3*DIMC*DIMC];       // tf32-rounded w_qkv
__device__ float g_wpr[(size_t)DIMC*DIMC];         // tf32-rounded w_proj

// ---------------------------------------------------------------------------
// helpers
// ---------------------------------------------------------------------------
__device__ __forceinline__ uint32_t smem_u32(const void* p) {
    uint32_t a;
    asm("{ .reg .u64 t; cvta.to.shared.u64 t, %1; cvt.u32.u64 %0, t; }" : "=r"(a) : "l"(p));
    return a;
}
__device__ __forceinline__ void cp16(uint32_t s, const void* g) {
    asm volatile("cp.async.ca.shared.global [%0], [%1], 16;" :: "r"(s), "l"(g) : "memory");
}
__device__ __forceinline__ void cp_commit() {
    asm volatile("cp.async.commit_group;" ::: "memory");
}
__device__ __forceinline__ void cp_wait1() {
    asm volatile("cp.async.wait_group 1;" ::: "memory");
}
__device__ __forceinline__ uint32_t f2tf(float x) {
    uint32_t r;
    asm("cvt.rna.tf32.f32 %0, %1;" : "=r"(r) : "f"(x));
    return r;
}
__device__ __forceinline__ void ldsm4(uint32_t& r0, uint32_t& r1, uint32_t& r2,
                                      uint32_t& r3, uint32_t addr) {
    asm volatile("ldmatrix.sync.aligned.m8n8.x4.shared.b16 {%0,%1,%2,%3}, [%4];"
                 : "=r"(r0), "=r"(r1), "=r"(r2), "=r"(r3) : "r"(addr));
}
__device__ __forceinline__ void mma_tf(float d[4], uint32_t a0, uint32_t a1,
                                       uint32_t a2, uint32_t a3,
                                       uint32_t b0, uint32_t b1) {
    asm volatile(
        "mma.sync.aligned.m16n8k8.row.col.f32.tf32.tf32.f32 "
        "{%0,%1,%2,%3},{%4,%5,%6,%7},{%8,%9},{%0,%1,%2,%3};"
        : "+f"(d[0]), "+f"(d[1]), "+f"(d[2]), "+f"(d[3])
        : "r"(a0), "r"(a1), "r"(a2), "r"(a3), "r"(b0), "r"(b1));
}

// ---------------------------------------------------------------------------
// round-to-tf32 copy
// ---------------------------------------------------------------------------
__global__ __launch_bounds__(256)
void round_tf_kernel(const float* __restrict__ src, float* __restrict__ dst, int n4)
{
    int i = blockIdx.x * blockDim.x + threadIdx.x;
    if (i < n4) {
        float4 v = ((const float4*)src)[i];
        v.x = __uint_as_float(f2tf(v.x));
        v.y = __uint_as_float(f2tf(v.y));
        v.z = __uint_as_float(f2tf(v.z));
        v.w = __uint_as_float(f2tf(v.w));
        ((float4*)dst)[i] = v;
    }
}

// ---------------------------------------------------------------------------
// GEMM: tf32 mma, CTA tile 128(M) x BN(N), 8 warps (2x4), warp tile 64x(BN/4).
// 3-stage cp.async ring, ldmatrix fragments.
// MODE 0: scatter into g_q/g_k/g_vt(transposed). MODE 1: write Cout.
// ---------------------------------------------------------------------------
#define GSTR 36                       // f32 row stride (32 + 4 pad)

template<int MODE, int BN>
__global__ __launch_bounds__(256, 1)
void gemm_tf32(const float* __restrict__ A, const float* __restrict__ W,
               const float* __restrict__ bias, float* __restrict__ Cout)
{
    constexpr int ASZ = 128 * GSTR;
    constexpr int WSZ = BN * GSTR;
    constexpr int STG = ASZ + WSZ;
    constexpr int WNW = BN / 4;       // warp n-width
    constexpr int NT  = WNW / 8;      // n-tiles per warp
    constexpr int NBK = WNW / 16;     // b ldsm4 count
    constexpr int NIT = (128 + BN) / 32;

    extern __shared__ float smf[];
    uint32_t smb = smem_u32(smf);

    int tid = threadIdx.x;
    int lane = tid & 31;
    int wid = tid >> 5;              // 0..7
    int g = lane >> 2, j = lane & 3;
    int wm = wid & 1, wn = wid >> 1; // 2 x 4 warp grid
    int m0 = blockIdx.y * 128;
    int n0 = blockIdx.x * BN;

    auto issue = [&](int c) {
        uint32_t stb = smb + (uint32_t)((c % 3) * STG) * 4;
#pragma unroll
        for (int it = 0; it < NIT; it++) {
            int f = tid + it * 256;
            int row = f >> 3;
            int c4 = (f & 7) * 4;
            if (it < 4) {
                cp16(stb + (uint32_t)(row * GSTR + c4) * 4,
                     A + (size_t)(m0 + row) * DIMC + c * 32 + c4);
            } else {
                int wrow = row - 128;
                cp16(stb + (uint32_t)(ASZ + wrow * GSTR + c4) * 4,
                     W + (size_t)(n0 + wrow) * DIMC + c * 32 + c4);
            }
        }
    };

    int aRowB = wm * 64 + ((lane >> 3) & 1) * 8 + (lane & 7);   // + mt*16
    int aColW = (lane >> 4) * 4;                                // + ks*8
    int bRowB = wn * WNW + ((lane >> 4) & 1) * 8 + (lane & 7);  // + bk*16
    int bColW = ((lane >> 3) & 1) * 4;                          // + ks*8

    float Cf[4][NT][4];
#pragma unroll
    for (int mt = 0; mt < 4; mt++)
#pragma unroll
        for (int nt = 0; nt < NT; nt++)
#pragma unroll
            for (int r = 0; r < 4; r++) Cf[mt][nt][r] = 0.f;

    issue(0); cp_commit();
    issue(1); cp_commit();

    const int NC = DIMC / 32;   // 24
    for (int c = 0; c < NC; c++) {
        cp_wait1();
        __syncthreads();
        if (c + 2 < NC) issue(c + 2);
        cp_commit();

        uint32_t stA = smb + (uint32_t)((c % 3) * STG) * 4;
        uint32_t stW = stA + (uint32_t)ASZ * 4;

#pragma unroll
        for (int ks = 0; ks < 4; ks++) {
            uint32_t a[4][4], b[NT][2];
#pragma unroll
            for (int mt = 0; mt < 4; mt++)
                ldsm4(a[mt][0], a[mt][1], a[mt][2], a[mt][3],
                      stA + (uint32_t)((aRowB + mt * 16) * GSTR + ks * 8 + aColW) * 4);
#pragma unroll
            for (int bk = 0; bk < NBK; bk++)
                ldsm4(b[2*bk][0], b[2*bk][1], b[2*bk+1][0], b[2*bk+1][1],
                      stW + (uint32_t)((bRowB + bk * 16) * GSTR + ks * 8 + bColW) * 4);
#pragma unroll
            for (int mt = 0; mt < 4; mt++)
#pragma unroll
                for (int nt = 0; nt < NT; nt++)
                    mma_tf(Cf[mt][nt], a[mt][0], a[mt][1], a[mt][2], a[mt][3],
                           b[nt][0], b[nt][1]);
        }
    }

    // epilogue
#pragma unroll
    for (int mt = 0; mt < 4; mt++) {
        int row0 = m0 + wm * 64 + mt * 16 + g;
#pragma unroll
        for (int nt = 0; nt < NT; nt++) {
            int col = n0 + wn * WNW + nt * 8 + 2 * j;
            float b0 = bias[col], b1 = bias[col + 1];
            float2 v0 = make_float2(Cf[mt][nt][0] + b0, Cf[mt][nt][1] + b1);
            float2 v1 = make_float2(Cf[mt][nt][2] + b0, Cf[mt][nt][3] + b1);
            if (MODE == 1) {
                *(float2*)(Cout + (size_t)row0 * DIMC + col) = v0;
                *(float2*)(Cout + (size_t)(row0 + 8) * DIMC + col) = v1;
            } else {
                int s = (col >= 2 * DIMC) ? 2 : (col >= DIMC ? 1 : 0);
                int rr = col - s * DIMC;
                int hh = rr / HD;
                int d = rr - hh * HD;
                int bb0 = row0 >> 11, t0 = row0 & (SEQ - 1);
                int r1 = row0 + 8;
                int bb1 = r1 >> 11, t1 = r1 & (SEQ - 1);
                if (s == 2) {
                    float* dv0 = g_vt + ((size_t)(bb0 * NH + hh) * HD + d) * SEQ + t0;
                    dv0[0] = v0.x; dv0[SEQ] = v0.y;
                    float* dv1 = g_vt + ((size_t)(bb1 * NH + hh) * HD + d) * SEQ + t1;
                    dv1[0] = v1.x; dv1[SEQ] = v1.y;
                } else {
                    float* base = (s == 0) ? g_q : g_k;
                    *(float2*)(base + ((size_t)(bb0 * NH + hh) * SEQ + t0) * HD + d) = v0;
                    *(float2*)(base + ((size_t)(bb1 * NH + hh) * SEQ + t1) * HD + d) = v1;
                }
            }
        }
    }
}

#define GEMM_SMEM_256 (3*(128+256)*GSTR*4)
#define GEMM_SMEM_128 (3*(128+128)*GSTR*4)

// ---------------------------------------------------------------------------
// RoPE in place on g_q, g_k.
// ---------------------------------------------------------------------------
__global__ __launch_bounds__(256)
void rope_kernel()
{
    int idx = blockIdx.x * blockDim.x + threadIdx.x;
    int j = idx % 48;
    int rest = idx / 48;
    int t = rest & (SEQ - 1);
    int bh = rest >> 11;

    float freq = exp2f(-(2.f * j / 96.f) * 13.287712379549449f);
    float ang = (float)t * freq;
    float sn, cs;
    sincosf(ang, &sn, &cs);

    size_t base = ((size_t)bh * SEQ + t) * HD;
    float q1 = g_q[base + j], q2 = g_q[base + j + 48];
    g_q[base + j]      = q1 * cs - q2 * sn;
    g_q[base + j + 48] = q2 * cs + q1 * sn;
    float k1 = g_k[base + j], k2 = g_k[base + j + 48];
    g_k[base + j]      = k1 * cs - k2 * sn;
    g_k[base + j + 48] = k2 * cs + k1 * sn;
}

// ---------------------------------------------------------------------------
// Flash attention (R8 structure): tf32 mma, ldmatrix frags, V pre-transposed,
// 3-stage cp.async K/Vt ring, ONE __syncthreads per K-tile (bottom sync was
// redundant: the next iteration's top sync fences all reads of the slot that
// prefetch overwrites).
// ---------------------------------------------------------------------------
#define QLD 100
#define KLD 100
#define VTLD 68
#define KVSTG (64*KLD + 96*VTLD)
#define ATTN_SMEM ((128*QLD + 3*KVSTG) * 4)   // 206336

__global__ __launch_bounds__(256, 1)
void attn_mma()
{
    extern __shared__ float smf[];
    float* Qs = smf;
    float* KV = smf + 128 * QLD;

    int qt = gridDim.x - 1 - blockIdx.x;
    int hh = blockIdx.y, b = blockIdx.z;
    int tid = threadIdx.x;
    int lane = tid & 31;
    int wid = tid >> 5;
    int g = lane >> 2, j = lane & 3;
    const float scale = rsqrtf((float)HD);

    const float* Qg = g_q + ((size_t)(b * NH + hh) * SEQ + (size_t)qt * 128) * HD;
    const float* Kg = g_k + ((size_t)(b * NH + hh) * SEQ) * HD;
    const float* Vtg = g_vt + ((size_t)(b * NH + hh) * HD) * SEQ;

    int nkt = 2 * qt + 2;

    auto issue_kv = [&](int kt) {
        int st = kt % 3;
        float* Ks = KV + st * KVSTG;
        float* Vs = Ks + 64 * KLD;
        const float* kp = Kg + (size_t)kt * 64 * HD;
#pragma unroll
        for (int it = 0; it < 6; it++) {
            int f = tid + it * 256;
            int r = f / 24, c4 = (f % 24) * 4;
            cp16(smem_u32(Ks + r * KLD + c4), kp + (size_t)r * HD + c4);
        }
        const float* vp = Vtg + kt * 64;
#pragma unroll
        for (int it = 0; it < 6; it++) {
            int f = tid + it * 256;
            int d = f >> 4, c4 = (f & 15) * 4;
            cp16(smem_u32(Vs + d * VTLD + c4), vp + (size_t)d * SEQ + c4);
        }
    };

    issue_kv(0); cp_commit();
    issue_kv(1); cp_commit();

    for (int f = tid; f < 128 * 24; f += 256) {
        int r = f / 24, c4 = (f % 24) * 4;
        float4 v = *(const float4*)(Qg + (size_t)r * HD + c4);
        v.x = __uint_as_float(f2tf(v.x * scale));
        v.y = __uint_as_float(f2tf(v.y * scale));
        v.z = __uint_as_float(f2tf(v.z * scale));
        v.w = __uint_as_float(f2tf(v.w * scale));
        *(float4*)(Qs + r * QLD + c4) = v;
    }

    uint32_t qsb = smem_u32(Qs);
    uint32_t kvb = smem_u32(KV);
    int qRow = wid * 16 + ((lane >> 3) & 1) * 8 + (lane & 7);
    int qColW = (lane >> 4) * 4;
    int bRow = ((lane >> 4) & 1) * 8 + (lane & 7);
    int bColW = ((lane >> 3) & 1) * 4;

    float m0r = -1e30f, m1r = -1e30f, l0r = 0.f, l1r = 0.f;
    float O[12][4];
#pragma unroll
    for (int nt = 0; nt < 12; nt++)
#pragma unroll
        for (int r = 0; r < 4; r++) O[nt][r] = 0.f;

    int row0 = qt * 128 + wid * 16 + g;
    int src_lo = (lane & ~3) | (j >> 1);
    int par = j & 1;

    for (int kt = 0; kt < nkt; kt++) {
        cp_wait1();
        __syncthreads();     // stage kt visible; all reads of slot (kt-1)%3 done
        if (kt + 2 < nkt) issue_kv(kt + 2);
        cp_commit();

        uint32_t ksb = kvb + (uint32_t)((kt % 3) * KVSTG) * 4;
        uint32_t vsb = ksb + (uint32_t)(64 * KLD) * 4;

        // ---- S = Q @ K^T ----
        float S[8][4];
#pragma unroll
        for (int nt = 0; nt < 8; nt++)
#pragma unroll
            for (int r = 0; r < 4; r++) S[nt][r] = 0.f;

#pragma unroll
        for (int ks = 0; ks < 12; ks++) {
            uint32_t a0, a1, a2, a3;
            ldsm4(a0, a1, a2, a3, qsb + (uint32_t)(qRow * QLD + ks * 8 + qColW) * 4);
            uint32_t bfr[8][2];
#pragma unroll
            for (int bk = 0; bk < 4; bk++)
                ldsm4(bfr[2*bk][0], bfr[2*bk][1], bfr[2*bk+1][0], bfr[2*bk+1][1],
                      ksb + (uint32_t)((bRow + bk * 16) * KLD + ks * 8 + bColW) * 4);
#pragma unroll
            for (int nt = 0; nt < 8; nt++)
                mma_tf(S[nt], a0, a1, a2, a3, bfr[nt][0], bfr[nt][1]);
        }

        if (kt >= nkt - 2) {
            int colb = kt * 64;
#pragma unroll
            for (int nt = 0; nt < 8; nt++) {
                int c0 = colb + nt * 8 + 2 * j;
                if (c0 > row0)     S[nt][0] = -1e30f;
                if (c0 + 1 > row0) S[nt][1] = -1e30f;
                if (c0 > row0 + 8)     S[nt][2] = -1e30f;
                if (c0 + 1 > row0 + 8) S[nt][3] = -1e30f;
            }
        }

        // ---- online softmax ----
        float mx0 = -1e30f, mx1 = -1e30f;
#pragma unroll
        for (int nt = 0; nt < 8; nt++) {
            mx0 = fmaxf(mx0, fmaxf(S[nt][0], S[nt][1]));
            mx1 = fmaxf(mx1, fmaxf(S[nt][2], S[nt][3]));
        }
        mx0 = fmaxf(mx0, __shfl_xor_sync(0xffffffffu, mx0, 1));
        mx0 = fmaxf(mx0, __shfl_xor_sync(0xffffffffu, mx0, 2));
        mx1 = fmaxf(mx1, __shfl_xor_sync(0xffffffffu, mx1, 1));
        mx1 = fmaxf(mx1, __shfl_xor_sync(0xffffffffu, mx1, 2));

        float mn0 = fmaxf(m0r, mx0), mn1 = fmaxf(m1r, mx1);
        float al0 = __expf(m0r - mn0), al1 = __expf(m1r - mn1);
        float s0 = 0.f, s1 = 0.f;
#pragma unroll
        for (int nt = 0; nt < 8; nt++) {
            S[nt][0] = __expf(S[nt][0] - mn0);
            S[nt][1] = __expf(S[nt][1] - mn0);
            S[nt][2] = __expf(S[nt][2] - mn1);
            S[nt][3] = __expf(S[nt][3] - mn1);
            s0 += S[nt][0] + S[nt][1];
            s1 += S[nt][2] + S[nt][3];
        }
        s0 += __shfl_xor_sync(0xffffffffu, s0, 1);
        s0 += __shfl_xor_sync(0xffffffffu, s0, 2);
        s1 += __shfl_xor_sync(0xffffffffu, s1, 1);
        s1 += __shfl_xor_sync(0xffffffffu, s1, 2);
        l0r = l0r * al0 + s0;
        l1r = l1r * al1 + s1;
        m0r = mn0; m1r = mn1;
#pragma unroll
        for (int nt = 0; nt < 12; nt++) {
            O[nt][0] *= al0; O[nt][1] *= al0;
            O[nt][2] *= al1; O[nt][3] *= al1;
        }

        // ---- O += P @ V ----
#pragma unroll
        for (int ks = 0; ks < 8; ks++) {
            float p00 = __shfl_sync(0xffffffffu, S[ks][0], src_lo);
            float p01 = __shfl_sync(0xffffffffu, S[ks][1], src_lo);
            float p10 = __shfl_sync(0xffffffffu, S[ks][0], src_lo + 2);
            float p11 = __shfl_sync(0xffffffffu, S[ks][1], src_lo + 2);
            float p20 = __shfl_sync(0xffffffffu, S[ks][2], src_lo);
            float p21 = __shfl_sync(0xffffffffu, S[ks][3], src_lo);
            float p30 = __shfl_sync(0xffffffffu, S[ks][2], src_lo + 2);
            float p31 = __shfl_sync(0xffffffffu, S[ks][3], src_lo + 2);
            uint32_t a0 = f2tf(par ? p01 : p00);
            uint32_t a1 = f2tf(par ? p21 : p20);
            uint32_t a2 = f2tf(par ? p11 : p10);
            uint32_t a3 = f2tf(par ? p31 : p30);
            uint32_t bfr[12][2];
#pragma unroll
            for (int bk = 0; bk < 6; bk++)
                ldsm4(bfr[2*bk][0], bfr[2*bk][1], bfr[2*bk+1][0], bfr[2*bk+1][1],
                      vsb + (uint32_t)((bRow + bk * 16) * VTLD + ks * 8 + bColW) * 4);
#pragma unroll
            for (int nt = 0; nt < 12; nt++)
                mma_tf(O[nt], a0, a1, a2, a3, bfr[nt][0], bfr[nt][1]);
        }
        // (no bottom sync: next iteration's top sync fences these reads)
    }

    float inv0 = 1.f / l0r, inv1 = 1.f / l1r;
    float* outb = g_att + ((size_t)b * SEQ + row0) * DIMC + hh * HD;
#pragma unroll
    for (int nt = 0; nt < 12; nt++) {
        int d = nt * 8 + 2 * j;
        float2 v0 = make_float2(__uint_as_float(f2tf(O[nt][0] * inv0)),
                                __uint_as_float(f2tf(O[nt][1] * inv0)));
        float2 v1 = make_float2(__uint_as_float(f2tf(O[nt][2] * inv1)),
                                __uint_as_float(f2tf(O[nt][3] * inv1)));
        *(float2*)(outb + d) = v0;
        *(float2*)(outb + (size_t)8 * DIMC + d) = v1;
    }
}

// ---------------------------------------------------------------------------
// Launch
// Inputs: 0=x, 1=mask (ignored, causal), 2=w_qkv, 3=b_qkv, 4=w_proj, 5=b_proj
// ---------------------------------------------------------------------------
extern "C" void kernel_launch(void* const* d_in, const int* in_sizes, int n_in,
                              void* d_out, int out_size)
{
    const float* x      = (const float*)d_in[0];
    const float* w_qkv  = (const float*)d_in[2];
    const float* b_qkv  = (const float*)d_in[3];
    const float* w_proj = (const float*)d_in[4];
    const float* b_proj = (const float*)d_in[5];
    float* out = (float*)d_out;

    cudaFuncSetAttribute(attn_mma, cudaFuncAttributeMaxDynamicSharedMemorySize,
                         ATTN_SMEM);
    cudaFuncSetAttribute((void*)gemm_tf32<0, 256>,
                         cudaFuncAttributeMaxDynamicSharedMemorySize, GEMM_SMEM_256);
    cudaFuncSetAttribute((void*)gemm_tf32<1, 128>,
                         cudaFuncAttributeMaxDynamicSharedMemorySize, GEMM_SMEM_128);

    float *xr, *wqr, *wpr, *attp;
    cudaGetSymbolAddress((void**)&xr,  g_xr);
    cudaGetSymbolAddress((void**)&wqr, g_wqr);
    cudaGetSymbolAddress((void**)&wpr, g_wpr);
    cudaGetSymbolAddress((void**)&attp, g_att);

    // tf32-round operands (removes truncation bias in mma)
    round_tf_kernel<<<(MTOT * DIMC / 4 + 255) / 256, 256>>>(x, xr, MTOT * DIMC / 4);
    round_tf_kernel<<<(3 * DIMC * DIMC / 4 + 255) / 256, 256>>>(w_qkv, wqr, 3 * DIMC * DIMC / 4);
    round_tf_kernel<<<(DIMC * DIMC / 4 + 255) / 256, 256>>>(w_proj, wpr, DIMC * DIMC / 4);

    // QKV: M=8192, N=2304 (CTA tile 128x256)
    gemm_tf32<0, 256><<<dim3(2304 / 256, MTOT / 128), 256, GEMM_SMEM_256>>>(
        xr, wqr, b_qkv, nullptr);

    // RoPE
    rope_kernel<<<(BATCH * NH * SEQ * 48) / 256, 256>>>();

    // Attention
    attn_mma<<<dim3(SEQ / 128, NH, BATCH), 256, ATTN_SMEM>>>();

    // Projection: M=8192, N=768 (CTA tile 128x128, 384 CTAs)
    gemm_tf32<1, 128><<<dim3(DIMC / 128, MTOT / 128), 256, GEMM_SMEM_128>>>(
        attp, wpr, b_proj, out);
}